// round 1
// baseline (speedup 1.0000x reference)
#include <cuda_runtime.h>

#define B_   2
#define S_   2048
#define D_   1024
#define H_   16
#define KS_  64
#define QKV_ 192   // 2*KS + VS per head
#define E_   (H_ * QKV_)  // 3072

// ---------------- scratch (device globals; no allocation allowed) -----------
__device__ float g_qkv [(size_t)B_ * S_ * E_];        // [B*S][3072]  h*192 + {q:0..63, k:64..127, v:128..191}
__device__ float g_vsuf[(size_t)B_ * H_ * S_ * KS_];  // [(b*H+h)*S + i][64] = sum_{j>i} V_j
__device__ float g_attn[(size_t)B_ * S_ * D_];        // [B*S][1024] (h*64 + d)
__device__ float g_y   [(size_t)B_ * S_ * D_];        // out-proj result

// ---------------- generic SGEMM: C[M,N] = A[M,K] @ B[K,N], row-major --------
// BM=BN=128, BK=8, 256 threads, 8x8 per-thread microtile.
__global__ __launch_bounds__(256) void sgemm_kernel(const float* __restrict__ A,
                                                    const float* __restrict__ Bm,
                                                    float* __restrict__ C,
                                                    int M, int N, int K) {
    __shared__ float As[8][128];   // transposed A tile
    __shared__ float Bs[8][128];
    int tid = threadIdx.x;
    int bx = blockIdx.x, by = blockIdx.y;
    A  += (size_t)by * 128 * K;
    Bm += (size_t)bx * 128;
    C  += (size_t)by * 128 * N + (size_t)bx * 128;

    int aRow = tid >> 1;            // 0..127
    int aCol = (tid & 1) << 2;      // 0 or 4
    int bRow = tid >> 5;            // 0..7
    int bCol = (tid & 31) << 2;     // 0..124
    int tRow = (tid >> 4) << 3;     // 0..120
    int tCol = (tid & 15) << 3;     // 0..120

    float acc[8][8] = {};
    for (int k0 = 0; k0 < K; k0 += 8) {
        float4 a4 = *(const float4*)(A + (size_t)aRow * K + k0 + aCol);
        As[aCol + 0][aRow] = a4.x;
        As[aCol + 1][aRow] = a4.y;
        As[aCol + 2][aRow] = a4.z;
        As[aCol + 3][aRow] = a4.w;
        *(float4*)(&Bs[bRow][bCol]) = *(const float4*)(Bm + (size_t)(k0 + bRow) * N + bCol);
        __syncthreads();
#pragma unroll
        for (int k = 0; k < 8; k++) {
            float rm[8], rn[8];
            *(float4*)(rm)     = *(const float4*)(&As[k][tRow]);
            *(float4*)(rm + 4) = *(const float4*)(&As[k][tRow + 4]);
            *(float4*)(rn)     = *(const float4*)(&Bs[k][tCol]);
            *(float4*)(rn + 4) = *(const float4*)(&Bs[k][tCol + 4]);
#pragma unroll
            for (int i = 0; i < 8; i++)
#pragma unroll
                for (int j = 0; j < 8; j++)
                    acc[i][j] += rm[i] * rn[j];
        }
        __syncthreads();
    }
#pragma unroll
    for (int i = 0; i < 8; i++)
#pragma unroll
        for (int j = 0; j < 8; j += 4) {
            float4 v = make_float4(acc[i][j], acc[i][j+1], acc[i][j+2], acc[i][j+3]);
            *(float4*)(C + (size_t)(tRow + i) * N + tCol + j) = v;
        }
}

// ---------------- suffix sums of V per (b,h):  vsuf[i] = sum_{j>i} V_j ------
// 32 blocks (b*H+h), 256 threads: d = tid&63, chunk c = tid>>6 (4 chunks of 512)
__global__ __launch_bounds__(256) void vsuf_kernel() {
    int bh = blockIdx.x;
    int b = bh >> 4, h = bh & 15;
    int tid = threadIdx.x;
    int d = tid & 63, c = tid >> 6;
    const int CH = S_ / 4;
    int start = c * CH, end = start + CH;
    __shared__ float tot[4][64];

    const float* vbase = g_qkv + (size_t)b * S_ * E_ + h * QKV_ + 128 + d;
    float* sbase = g_vsuf + (size_t)bh * S_ * 64 + d;

    float acc = 0.f;
#pragma unroll 4
    for (int i = end - 1; i >= start; i--) {
        sbase[(size_t)i * 64] = acc;            // local suffix within chunk
        acc += vbase[(size_t)i * (size_t)E_];
    }
    tot[c][d] = acc;
    __syncthreads();
    if (c < 3) {
        float carry = 0.f;
        for (int cc = c + 1; cc < 4; cc++) carry += tot[cc][d];
#pragma unroll 4
        for (int i = start; i < end; i++)
            sbase[(size_t)i * 64] += carry;
    }
}

// ---------------- flash attention (causal half) + zero-mass correction ------
// Block: (qt, h, b) — 64 queries. 256 threads. 48KB smem exactly.
__global__ __launch_bounds__(256) void attn_kernel() {
    int qt = blockIdx.x;   // 0..31
    int h  = blockIdx.y;
    int b  = blockIdx.z;

    __shared__ float Qt[64][64];   // [d][r]  (Q transposed, pre-scaled)
    __shared__ float KP[64][64];   // Kt [d][j], later reused as Pt [j][r]
    __shared__ float Vs[64][64];   // [j][d]

    int tid = threadIdx.x;
    int lr = tid >> 2;          // load row 0..63
    int lg = (tid & 3) << 4;    // load col offset 0,16,32,48
    int r0 = (tid >> 4) << 2;   // compute rows 0..60
    int c0 = (tid & 15) << 2;   // compute cols 0..60
    const float scale = 0.125f; // KS^-0.5

    // load Q (transposed + scaled)
    {
        const float* qp = g_qkv + ((size_t)(b * S_ + qt * 64 + lr)) * E_ + h * QKV_ + lg;
#pragma unroll
        for (int v = 0; v < 4; v++) {
            float4 t = *(const float4*)(qp + v * 4);
            Qt[lg + v*4 + 0][lr] = t.x * scale;
            Qt[lg + v*4 + 1][lr] = t.y * scale;
            Qt[lg + v*4 + 2][lr] = t.z * scale;
            Qt[lg + v*4 + 3][lr] = t.w * scale;
        }
    }

    float acc[4][4] = {};
    float m[4] = {0.f, 0.f, 0.f, 0.f};   // init 0: zero-score entries' max, exact shift
    float l[4] = {0.f, 0.f, 0.f, 0.f};

    for (int kt = 0; kt <= qt; kt++) {
        __syncthreads();  // previous Pt/Vs consumed (also orders Qt stores on first iter)
        {   // load K transposed + V natural (key rows j = kt*64 + lr)
            const float* kp = g_qkv + ((size_t)(b * S_ + kt * 64 + lr)) * E_ + h * QKV_ + 64 + lg;
#pragma unroll
            for (int v = 0; v < 4; v++) {
                float4 t = *(const float4*)(kp + v * 4);
                KP[lg + v*4 + 0][lr] = t.x;
                KP[lg + v*4 + 1][lr] = t.y;
                KP[lg + v*4 + 2][lr] = t.z;
                KP[lg + v*4 + 3][lr] = t.w;
                float4 u = *(const float4*)(kp + 64 + v * 4);
                *(float4*)(&Vs[lr][lg + v*4]) = u;
            }
        }
        __syncthreads();

        // scores s[i][j] = q(r0+i) . k(c0+j)
        float s[4][4] = {};
#pragma unroll 8
        for (int d = 0; d < 64; d++) {
            float rm[4], rn[4];
            *(float4*)rm = *(const float4*)(&Qt[d][r0]);
            *(float4*)rn = *(const float4*)(&KP[d][c0]);
#pragma unroll
            for (int i = 0; i < 4; i++)
#pragma unroll
                for (int j = 0; j < 4; j++)
                    s[i][j] += rm[i] * rn[j];
        }
        __syncthreads();  // done reading Kt; KP reusable for Pt

        if (kt == qt) {   // diagonal tile: future keys are the zero-score set
#pragma unroll
            for (int i = 0; i < 4; i++)
#pragma unroll
                for (int j = 0; j < 4; j++)
                    if (c0 + j > r0 + i) s[i][j] = -1e30f;  // exp -> 0
        }

        // online softmax per row (group = 16 lanes sharing r0)
#pragma unroll
        for (int i = 0; i < 4; i++) {
            float mx = fmaxf(fmaxf(s[i][0], s[i][1]), fmaxf(s[i][2], s[i][3]));
#pragma unroll
            for (int o = 1; o < 16; o <<= 1)
                mx = fmaxf(mx, __shfl_xor_sync(0xffffffffu, mx, o));
            float mn = fmaxf(m[i], mx);
            float corr = __expf(m[i] - mn);
            m[i] = mn;
            float rs = 0.f;
#pragma unroll
            for (int j = 0; j < 4; j++) {
                float p = __expf(s[i][j] - mn);
                s[i][j] = p;
                rs += p;
            }
#pragma unroll
            for (int o = 1; o < 16; o <<= 1)
                rs += __shfl_xor_sync(0xffffffffu, rs, o);
            l[i] = l[i] * corr + rs;
#pragma unroll
            for (int j = 0; j < 4; j++) acc[i][j] *= corr;
        }

        // store Pt[j][r]
#pragma unroll
        for (int i = 0; i < 4; i++)
#pragma unroll
            for (int j = 0; j < 4; j++)
                KP[c0 + j][r0 + i] = s[i][j];
        __syncthreads();

        // PV: acc[i][c] += sum_j Pt[j][r0+i] * Vs[j][c0+c]
#pragma unroll 8
        for (int j = 0; j < 64; j++) {
            float rm[4], rn[4];
            *(float4*)rm = *(const float4*)(&KP[j][r0]);
            *(float4*)rn = *(const float4*)(&Vs[j][c0]);
#pragma unroll
            for (int i = 0; i < 4; i++)
#pragma unroll
                for (int cdim = 0; cdim < 4; cdim++)
                    acc[i][cdim] += rm[i] * rn[cdim];
        }
    }

    // finalize: zero-score mass (count = S-1-qi, weight exp(-m)) + suffix-V
#pragma unroll
    for (int i = 0; i < 4; i++) {
        int qi = qt * 64 + r0 + i;
        float w0 = __expf(-m[i]);
        float denom = l[i] + (float)(S_ - 1 - qi) * w0;
        const float* vs = g_vsuf + ((size_t)(b * H_ + h) * S_ + qi) * 64 + c0;
        float4 sv = *(const float4*)vs;
        float inv = 1.f / denom;
        float4 o;
        o.x = (acc[i][0] + w0 * sv.x) * inv;
        o.y = (acc[i][1] + w0 * sv.y) * inv;
        o.z = (acc[i][2] + w0 * sv.z) * inv;
        o.w = (acc[i][3] + w0 * sv.w) * inv;
        *(float4*)(g_attn + ((size_t)(b * S_ + qi)) * D_ + h * 64 + c0) = o;
    }
}

// ---------------- residual + LayerNorm (eps = 1e-3, biased var) -------------
__global__ __launch_bounds__(256) void ln_kernel(const float* __restrict__ x,
                                                 const float* __restrict__ gamma,
                                                 const float* __restrict__ beta,
                                                 float* __restrict__ out) {
    int row = blockIdx.x;
    int tid = threadIdx.x;
    const float* xr = x + (size_t)row * D_;
    const float* yr = g_y + (size_t)row * D_;
    float4 xv = *(const float4*)(xr + tid * 4);
    float4 yv = *(const float4*)(yr + tid * 4);
    float v0 = xv.x + yv.x, v1 = xv.y + yv.y, v2 = xv.z + yv.z, v3 = xv.w + yv.w;
    float sum = v0 + v1 + v2 + v3;
    float sq  = v0*v0 + v1*v1 + v2*v2 + v3*v3;
#pragma unroll
    for (int o = 16; o >= 1; o >>= 1) {
        sum += __shfl_xor_sync(0xffffffffu, sum, o);
        sq  += __shfl_xor_sync(0xffffffffu, sq, o);
    }
    __shared__ float ssum[8], ssq[8];
    int wid = tid >> 5, lane = tid & 31;
    if (lane == 0) { ssum[wid] = sum; ssq[wid] = sq; }
    __syncthreads();
    float ts = 0.f, tq = 0.f;
#pragma unroll
    for (int w = 0; w < 8; w++) { ts += ssum[w]; tq += ssq[w]; }
    float mean = ts * (1.f / 1024.f);
    float var  = tq * (1.f / 1024.f) - mean * mean;
    float rstd = rsqrtf(var + 1e-3f);
    int c = tid * 4;
    float4 g4 = *(const float4*)(gamma + c);
    float4 b4 = *(const float4*)(beta + c);
    float4 o;
    o.x = (v0 - mean) * rstd * g4.x + b4.x;
    o.y = (v1 - mean) * rstd * g4.y + b4.y;
    o.z = (v2 - mean) * rstd * g4.z + b4.z;
    o.w = (v3 - mean) * rstd * g4.w + b4.w;
    *(float4*)(out + (size_t)row * D_ + c) = o;
}

// ---------------- launch ----------------------------------------------------
extern "C" void kernel_launch(void* const* d_in, const int* in_sizes, int n_in,
                              void* d_out, int out_size) {
    const float* x       = (const float*)d_in[0];
    // d_in[1] = mask (multiplicative tril) — structure exploited analytically
    const float* W_embed = (const float*)d_in[2];
    const float* W_out   = (const float*)d_in[3];
    const float* gamma   = (const float*)d_in[4];
    const float* beta    = (const float*)d_in[5];
    float* out = (float*)d_out;

    float *qkv, *attn, *y;
    cudaGetSymbolAddress((void**)&qkv,  g_qkv);
    cudaGetSymbolAddress((void**)&attn, g_attn);
    cudaGetSymbolAddress((void**)&y,    g_y);

    // 1) QKV projection: [4096,1024] @ [1024,3072]
    sgemm_kernel<<<dim3(E_ / 128, (B_ * S_) / 128), 256>>>(x, W_embed, qkv,
                                                           B_ * S_, E_, D_);
    // 2) suffix sums of V per (b,h)
    vsuf_kernel<<<B_ * H_, 256>>>();
    // 3) attention
    attn_kernel<<<dim3(S_ / 64, H_, B_), 256>>>();
    // 4) out projection: [4096,1024] @ [1024,1024]
    sgemm_kernel<<<dim3(D_ / 128, (B_ * S_) / 128), 256>>>(attn, W_out, y,
                                                           B_ * S_, D_, D_);
    // 5) residual + layernorm
    ln_kernel<<<B_ * S_, 256>>>(x, gamma, beta, out);
}

// round 3
// speedup vs baseline: 1.3765x; 1.3765x over previous
#include <cuda_runtime.h>
#include <cuda_bf16.h>
#include <cstdint>

#define B_   2
#define S_   2048
#define D_   1024
#define H_   16
#define KS_  64
#define QKV_ 192
#define E_   (H_ * QKV_)  // 3072
#define MS_  (B_ * S_)    // 4096

// ---------------- scratch (device globals; no allocation allowed) -----------
__device__ float g_qkv [(size_t)MS_ * E_];
__device__ float g_vsuf[(size_t)B_ * H_ * S_ * KS_];
__device__ float g_attn[(size_t)MS_ * D_];
__device__ float g_y   [(size_t)MS_ * D_];

__device__ __nv_bfloat16 g_xhi [(size_t)MS_ * D_];
__device__ __nv_bfloat16 g_xlo [(size_t)MS_ * D_];
__device__ __nv_bfloat16 g_ahi [(size_t)MS_ * D_];
__device__ __nv_bfloat16 g_alo [(size_t)MS_ * D_];
__device__ __nv_bfloat16 g_weThi[(size_t)E_ * D_];
__device__ __nv_bfloat16 g_weTlo[(size_t)E_ * D_];
__device__ __nv_bfloat16 g_woThi[(size_t)D_ * D_];
__device__ __nv_bfloat16 g_woTlo[(size_t)D_ * D_];

// ---------------- helpers ----------------------------------------------------
__device__ __forceinline__ uint32_t s2u(const void* p) {
    uint32_t a;
    asm("{ .reg .u64 t; cvta.to.shared.u64 t, %1; cvt.u32.u64 %0, t; }" : "=r"(a) : "l"(p));
    return a;
}
#define CP16(d, g) asm volatile("cp.async.cg.shared.global [%0], [%1], 16;" :: "r"(d), "l"(g))
#define LDSM4(r, a) \
    asm volatile("ldmatrix.sync.aligned.m8n8.x4.shared.b16 {%0,%1,%2,%3}, [%4];" \
                 : "=r"((r)[0]), "=r"((r)[1]), "=r"((r)[2]), "=r"((r)[3]) : "r"(a))
#define MMA16816(d, a, b) \
    asm volatile("mma.sync.aligned.m16n8k16.row.col.f32.bf16.bf16.f32 " \
                 "{%0,%1,%2,%3}, {%4,%5,%6,%7}, {%8,%9}, {%0,%1,%2,%3};" \
                 : "+f"((d)[0]), "+f"((d)[1]), "+f"((d)[2]), "+f"((d)[3]) \
                 : "r"((a)[0]), "r"((a)[1]), "r"((a)[2]), "r"((a)[3]), \
                   "r"((b)[0]), "r"((b)[1]))

// ---------------- HMMA GEMM: C[M,N] = A[M,K] @ Bt[N,K]^T (bf16 hi/lo) -------
// CTA 128x128, BK=64, 3-stage cp.async, 8 warps (warp tile 32x64).
// smem rows padded to 144B -> conflict-free ldmatrix.
#define MATB 18432            // 128 rows * 144 B
#define STG  (4 * MATB)       // Ahi, Alo, Bhi, Blo per stage
#define SMEM_GEMM (3 * STG)   // 221184 B

__global__ __launch_bounds__(256) void hmma_gemm_kernel(
    const __nv_bfloat16* __restrict__ Ahi, const __nv_bfloat16* __restrict__ Alo,
    const __nv_bfloat16* __restrict__ Bhi, const __nv_bfloat16* __restrict__ Blo,
    float* __restrict__ C, int Ntot, int Ktot)
{
    extern __shared__ __align__(128) char smem_raw[];
    uint32_t sb = s2u(smem_raw);
    const int tid = threadIdx.x, lane = tid & 31, wid = tid >> 5;
    const int warpM = wid & 3, warpN = wid >> 2;       // 4 x 2 warp grid
    const int m0 = blockIdx.y * 128, n0 = blockIdx.x * 128;
    const int NC = Ktot >> 6;                           // K chunks of 64
    const size_t rowb = (size_t)Ktot * 2;               // global row stride bytes

    const char* srcs[4] = {
        (const char*)(Ahi + (size_t)m0 * Ktot), (const char*)(Alo + (size_t)m0 * Ktot),
        (const char*)(Bhi + (size_t)n0 * Ktot), (const char*)(Blo + (size_t)n0 * Ktot) };

    auto issue = [&](int c) {
        uint32_t base = sb + (uint32_t)(c % 3) * STG;
        size_t gk = (size_t)c * 128;                    // 64 bf16 = 128 B
        #pragma unroll
        for (int t = 0; t < 4; t++) {
            #pragma unroll
            for (int it = 0; it < 4; it++) {
                int idx = tid + it * 256;
                int row = idx >> 3, seg = idx & 7;
                const char* g = srcs[t] + (size_t)row * rowb + gk + seg * 16;
                uint32_t d = base + t * MATB + row * 144 + seg * 16;
                CP16(d, g);
            }
        }
        asm volatile("cp.async.commit_group;" ::: "memory");
    };

    issue(0);
    issue(1);

    float acc[2][8][4] = {};

    for (int c = 0; c < NC; c++) {
        if (c + 2 < NC) {
            issue(c + 2);                               // buffer (c+2)%3 == (c-1)%3: free
            asm volatile("cp.async.wait_group 2;" ::: "memory");
        } else if (c + 1 < NC) {
            asm volatile("cp.async.wait_group 1;" ::: "memory");
        } else {
            asm volatile("cp.async.wait_group 0;" ::: "memory");
        }
        __syncthreads();

        uint32_t st = sb + (uint32_t)(c % 3) * STG;
        #pragma unroll
        for (int ks = 0; ks < 4; ks++) {
            uint32_t ah[2][4], al[2][4], bh[4][4], bl[4][4];
            #pragma unroll
            for (int mb = 0; mb < 2; mb++) {
                uint32_t ad = st + (uint32_t)((warpM * 32 + mb * 16 + (lane & 15)) * 144
                                              + ((lane >> 4) << 4) + ks * 32);
                LDSM4(ah[mb], ad);
                LDSM4(al[mb], ad + MATB);
            }
            #pragma unroll
            for (int nb = 0; nb < 4; nb++) {
                uint32_t bd = st + 2 * MATB
                            + (uint32_t)((warpN * 64 + nb * 16 + (lane & 7) + ((lane >> 4) << 3)) * 144
                                         + (((lane >> 3) & 1) << 4) + ks * 32);
                LDSM4(bh[nb], bd);
                LDSM4(bl[nb], bd + MATB);
            }
            #pragma unroll
            for (int mb = 0; mb < 2; mb++)
                #pragma unroll
                for (int j = 0; j < 8; j++) {
                    uint32_t* bhp = &bh[j >> 1][(j & 1) * 2];
                    uint32_t* blp = &bl[j >> 1][(j & 1) * 2];
                    MMA16816(acc[mb][j], ah[mb], bhp);
                    MMA16816(acc[mb][j], al[mb], bhp);
                    MMA16816(acc[mb][j], ah[mb], blp);
                }
        }
        __syncthreads();
    }

    // epilogue
    const int r = lane >> 2, cp = (lane & 3) * 2;
    #pragma unroll
    for (int mb = 0; mb < 2; mb++)
        #pragma unroll
        for (int j = 0; j < 8; j++) {
            int row = m0 + warpM * 32 + mb * 16 + r;
            int col = n0 + warpN * 64 + j * 8 + cp;
            float* p0 = C + (size_t)row * Ntot + col;
            float* p1 = C + (size_t)(row + 8) * Ntot + col;
            p0[0] = acc[mb][j][0]; p0[1] = acc[mb][j][1];
            p1[0] = acc[mb][j][2]; p1[1] = acc[mb][j][3];
        }
}

// ---------------- fp32 -> bf16 hi/lo split -----------------------------------
__global__ __launch_bounds__(256) void split_kernel(const float* __restrict__ src,
                                                    __nv_bfloat16* __restrict__ hi,
                                                    __nv_bfloat16* __restrict__ lo, int n4) {
    int i = blockIdx.x * 256 + threadIdx.x;
    if (i >= n4) return;
    float4 v = ((const float4*)src)[i];
    float vs[4] = {v.x, v.y, v.z, v.w};
    __nv_bfloat16 h[4], l[4];
    #pragma unroll
    for (int k = 0; k < 4; k++) {
        h[k] = __float2bfloat16(vs[k]);
        l[k] = __float2bfloat16(vs[k] - __bfloat162float(h[k]));
    }
    ((__nv_bfloat162*)hi)[i*2+0] = __nv_bfloat162(h[0], h[1]);
    ((__nv_bfloat162*)hi)[i*2+1] = __nv_bfloat162(h[2], h[3]);
    ((__nv_bfloat162*)lo)[i*2+0] = __nv_bfloat162(l[0], l[1]);
    ((__nv_bfloat162*)lo)[i*2+1] = __nv_bfloat162(l[2], l[3]);
}

// ---------------- W[K,N] -> W^T[N,K] hi/lo -----------------------------------
__global__ __launch_bounds__(256) void tsplit_kernel(const float* __restrict__ W,
                                                     __nv_bfloat16* __restrict__ Thi,
                                                     __nv_bfloat16* __restrict__ Tlo,
                                                     int K, int N) {
    __shared__ float tile[32][33];
    int tx = threadIdx.x & 31, ty = threadIdx.x >> 5;
    int k0 = blockIdx.y * 32, n0 = blockIdx.x * 32;
    #pragma unroll
    for (int r = ty; r < 32; r += 8)
        tile[r][tx] = W[(size_t)(k0 + r) * N + n0 + tx];
    __syncthreads();
    #pragma unroll
    for (int r = ty; r < 32; r += 8) {
        float v = tile[tx][r];
        __nv_bfloat16 h = __float2bfloat16(v);
        __nv_bfloat16 l = __float2bfloat16(v - __bfloat162float(h));
        size_t o = (size_t)(n0 + r) * K + k0 + tx;
        Thi[o] = h; Tlo[o] = l;
    }
}

// ---------------- suffix sums of V per (b,h) ---------------------------------
__global__ __launch_bounds__(256) void vsuf_kernel() {
    int bh = blockIdx.x;
    int b = bh >> 4, h = bh & 15;
    int tid = threadIdx.x;
    int d = tid & 63, c = tid >> 6;
    const int CH = S_ / 4;
    int start = c * CH, end = start + CH;
    __shared__ float tot[4][64];

    const float* vbase = g_qkv + (size_t)b * S_ * E_ + h * QKV_ + 128 + d;
    float* sbase = g_vsuf + (size_t)bh * S_ * 64 + d;

    float acc = 0.f;
#pragma unroll 4
    for (int i = end - 1; i >= start; i--) {
        sbase[(size_t)i * 64] = acc;
        acc += vbase[(size_t)i * (size_t)E_];
    }
    tot[c][d] = acc;
    __syncthreads();
    if (c < 3) {
        float carry = 0.f;
        for (int cc = c + 1; cc < 4; cc++) carry += tot[cc][d];
#pragma unroll 4
        for (int i = start; i < end; i++)
            sbase[(size_t)i * 64] += carry;
    }
}

// ---------------- flash attention (causal half) + zero-mass correction ------
__global__ __launch_bounds__(256) void attn_kernel() {
    int qt = blockIdx.x;
    int h  = blockIdx.y;
    int b  = blockIdx.z;

    __shared__ float Qt[64][64];
    __shared__ float KP[64][64];
    __shared__ float Vs[64][64];

    int tid = threadIdx.x;
    int lr = tid >> 2;
    int lg = (tid & 3) << 4;
    int r0 = (tid >> 4) << 2;
    int c0 = (tid & 15) << 2;
    const float scale = 0.125f;

    {
        const float* qp = g_qkv + ((size_t)(b * S_ + qt * 64 + lr)) * E_ + h * QKV_ + lg;
#pragma unroll
        for (int v = 0; v < 4; v++) {
            float4 t = *(const float4*)(qp + v * 4);
            Qt[lg + v*4 + 0][lr] = t.x * scale;
            Qt[lg + v*4 + 1][lr] = t.y * scale;
            Qt[lg + v*4 + 2][lr] = t.z * scale;
            Qt[lg + v*4 + 3][lr] = t.w * scale;
        }
    }

    float acc[4][4] = {};
    float m[4] = {0.f, 0.f, 0.f, 0.f};
    float l[4] = {0.f, 0.f, 0.f, 0.f};

    for (int kt = 0; kt <= qt; kt++) {
        __syncthreads();
        {
            const float* kp = g_qkv + ((size_t)(b * S_ + kt * 64 + lr)) * E_ + h * QKV_ + 64 + lg;
#pragma unroll
            for (int v = 0; v < 4; v++) {
                float4 t = *(const float4*)(kp + v * 4);
                KP[lg + v*4 + 0][lr] = t.x;
                KP[lg + v*4 + 1][lr] = t.y;
                KP[lg + v*4 + 2][lr] = t.z;
                KP[lg + v*4 + 3][lr] = t.w;
                float4 u = *(const float4*)(kp + 64 + v * 4);
                *(float4*)(&Vs[lr][lg + v*4]) = u;
            }
        }
        __syncthreads();

        float s[4][4] = {};
#pragma unroll 8
        for (int d = 0; d < 64; d++) {
            float rm[4], rn[4];
            *(float4*)rm = *(const float4*)(&Qt[d][r0]);
            *(float4*)rn = *(const float4*)(&KP[d][c0]);
#pragma unroll
            for (int i = 0; i < 4; i++)
#pragma unroll
                for (int j = 0; j < 4; j++)
                    s[i][j] += rm[i] * rn[j];
        }
        __syncthreads();

        if (kt == qt) {
#pragma unroll
            for (int i = 0; i < 4; i++)
#pragma unroll
                for (int j = 0; j < 4; j++)
                    if (c0 + j > r0 + i) s[i][j] = -1e30f;
        }

#pragma unroll
        for (int i = 0; i < 4; i++) {
            float mx = fmaxf(fmaxf(s[i][0], s[i][1]), fmaxf(s[i][2], s[i][3]));
#pragma unroll
            for (int o = 1; o < 16; o <<= 1)
                mx = fmaxf(mx, __shfl_xor_sync(0xffffffffu, mx, o));
            float mn = fmaxf(m[i], mx);
            float corr = __expf(m[i] - mn);
            m[i] = mn;
            float rs = 0.f;
#pragma unroll
            for (int j = 0; j < 4; j++) {
                float p = __expf(s[i][j] - mn);
                s[i][j] = p;
                rs += p;
            }
#pragma unroll
            for (int o = 1; o < 16; o <<= 1)
                rs += __shfl_xor_sync(0xffffffffu, rs, o);
            l[i] = l[i] * corr + rs;
#pragma unroll
            for (int j = 0; j < 4; j++) acc[i][j] *= corr;
        }

#pragma unroll
        for (int i = 0; i < 4; i++)
#pragma unroll
            for (int j = 0; j < 4; j++)
                KP[c0 + j][r0 + i] = s[i][j];
        __syncthreads();

#pragma unroll 8
        for (int j = 0; j < 64; j++) {
            float rm[4], rn[4];
            *(float4*)rm = *(const float4*)(&KP[j][r0]);
            *(float4*)rn = *(const float4*)(&Vs[j][c0]);
#pragma unroll
            for (int i = 0; i < 4; i++)
#pragma unroll
                for (int cdim = 0; cdim < 4; cdim++)
                    acc[i][cdim] += rm[i] * rn[cdim];
        }
    }

#pragma unroll
    for (int i = 0; i < 4; i++) {
        int qi = qt * 64 + r0 + i;
        float w0 = __expf(-m[i]);
        float denom = l[i] + (float)(S_ - 1 - qi) * w0;
        const float* vs = g_vsuf + ((size_t)(b * H_ + h) * S_ + qi) * 64 + c0;
        float4 sv = *(const float4*)vs;
        float inv = 1.f / denom;
        float4 o;
        o.x = (acc[i][0] + w0 * sv.x) * inv;
        o.y = (acc[i][1] + w0 * sv.y) * inv;
        o.z = (acc[i][2] + w0 * sv.z) * inv;
        o.w = (acc[i][3] + w0 * sv.w) * inv;
        *(float4*)(g_attn + ((size_t)(b * S_ + qi)) * D_ + h * 64 + c0) = o;
    }
}

// ---------------- residual + LayerNorm ---------------------------------------
__global__ __launch_bounds__(256) void ln_kernel(const float* __restrict__ x,
                                                 const float* __restrict__ gamma,
                                                 const float* __restrict__ beta,
                                                 float* __restrict__ out) {
    int row = blockIdx.x;
    int tid = threadIdx.x;
    const float* xr = x + (size_t)row * D_;
    const float* yr = g_y + (size_t)row * D_;
    float4 xv = *(const float4*)(xr + tid * 4);
    float4 yv = *(const float4*)(yr + tid * 4);
    float v0 = xv.x + yv.x, v1 = xv.y + yv.y, v2 = xv.z + yv.z, v3 = xv.w + yv.w;
    float sum = v0 + v1 + v2 + v3;
    float sq  = v0*v0 + v1*v1 + v2*v2 + v3*v3;
#pragma unroll
    for (int o = 16; o >= 1; o >>= 1) {
        sum += __shfl_xor_sync(0xffffffffu, sum, o);
        sq  += __shfl_xor_sync(0xffffffffu, sq, o);
    }
    __shared__ float ssum[8], ssq[8];
    int wid = tid >> 5, lane = tid & 31;
    if (lane == 0) { ssum[wid] = sum; ssq[wid] = sq; }
    __syncthreads();
    float ts = 0.f, tq = 0.f;
#pragma unroll
    for (int w = 0; w < 8; w++) { ts += ssum[w]; tq += ssq[w]; }
    float mean = ts * (1.f / 1024.f);
    float var  = tq * (1.f / 1024.f) - mean * mean;
    float rstd = rsqrtf(var + 1e-3f);
    int c = tid * 4;
    float4 g4 = *(const float4*)(gamma + c);
    float4 b4 = *(const float4*)(beta + c);
    float4 o;
    o.x = (v0 - mean) * rstd * g4.x + b4.x;
    o.y = (v1 - mean) * rstd * g4.y + b4.y;
    o.z = (v2 - mean) * rstd * g4.z + b4.z;
    o.w = (v3 - mean) * rstd * g4.w + b4.w;
    *(float4*)(out + (size_t)row * D_ + c) = o;
}

// ---------------- launch ------------------------------------------------------
extern "C" void kernel_launch(void* const* d_in, const int* in_sizes, int n_in,
                              void* d_out, int out_size) {
    const float* x       = (const float*)d_in[0];
    const float* W_embed = (const float*)d_in[2];
    const float* W_out   = (const float*)d_in[3];
    const float* gamma   = (const float*)d_in[4];
    const float* beta    = (const float*)d_in[5];
    float* out = (float*)d_out;

    float *qkv, *attn, *y;
    cudaGetSymbolAddress((void**)&qkv,  g_qkv);
    cudaGetSymbolAddress((void**)&attn, g_attn);
    cudaGetSymbolAddress((void**)&y,    g_y);
    __nv_bfloat16 *xhi, *xlo, *ahi, *alo, *weThi, *weTlo, *woThi, *woTlo;
    cudaGetSymbolAddress((void**)&xhi, g_xhi);
    cudaGetSymbolAddress((void**)&xlo, g_xlo);
    cudaGetSymbolAddress((void**)&ahi, g_ahi);
    cudaGetSymbolAddress((void**)&alo, g_alo);
    cudaGetSymbolAddress((void**)&weThi, g_weThi);
    cudaGetSymbolAddress((void**)&weTlo, g_weTlo);
    cudaGetSymbolAddress((void**)&woThi, g_woThi);
    cudaGetSymbolAddress((void**)&woTlo, g_woTlo);

    cudaFuncSetAttribute(hmma_gemm_kernel,
                         cudaFuncAttributeMaxDynamicSharedMemorySize, SMEM_GEMM);

    // 0) bf16 hi/lo splits of x and transposed weights
    split_kernel<<<(MS_ * D_ / 4 + 255) / 256, 256>>>(x, xhi, xlo, MS_ * D_ / 4);
    tsplit_kernel<<<dim3(E_ / 32, D_ / 32), 256>>>(W_embed, weThi, weTlo, D_, E_);
    tsplit_kernel<<<dim3(D_ / 32, D_ / 32), 256>>>(W_out,   woThi, woTlo, D_, D_);

    // 1) QKV projection (HMMA): [4096,1024] @ [1024,3072]
    hmma_gemm_kernel<<<dim3(E_ / 128, MS_ / 128), 256, SMEM_GEMM>>>(
        xhi, xlo, weThi, weTlo, qkv, E_, D_);
    // 2) suffix sums of V
    vsuf_kernel<<<B_ * H_, 256>>>();
    // 3) attention (fp32 SIMT — Round 3 target)
    attn_kernel<<<dim3(S_ / 64, H_, B_), 256>>>();
    // 4) split attention output, out projection (HMMA)
    split_kernel<<<(MS_ * D_ / 4 + 255) / 256, 256>>>(attn, ahi, alo, MS_ * D_ / 4);
    hmma_gemm_kernel<<<dim3(D_ / 128, MS_ / 128), 256, SMEM_GEMM>>>(
        ahi, alo, woThi, woTlo, y, D_, D_);
    // 5) residual + layernorm
    ln_kernel<<<MS_, 256>>>(x, gamma, beta, out);
}